// round 4
// baseline (speedup 1.0000x reference)
#include <cuda_runtime.h>
#include <math.h>

#define NN 50000
#define NE 800000
#define DIM 128
#define NH 8
#define HD 16
#define NET 5

// ---- scratch (device globals; no allocation allowed) ----
__device__ float gQ[NN * DIM];
__device__ float gK[NN * DIM];
__device__ float gV[NN * DIM];
__device__ float gAgg[NN * DIM];
__device__ float gHid[NN * DIM];
__device__ float gF1[NN * 4 * DIM];
__device__ int   gEid[NE];
__device__ int   gCnt[NN];
__device__ int   gCur[NN];
__device__ int   gRow[NN + 1];
__device__ int   gBlkSum[64];
__device__ int   gBlkOff[64];

// ---------------------------------------------------------------------------
__global__ void init_kernel(int N) {
    int i = blockIdx.x * blockDim.x + threadIdx.x;
    if (i < N) { gCnt[i] = 0; gCur[i] = 0; }
}

// ---------------------------------------------------------------------------
// per-node-type QKV: one block (128 thr) per node; thread = (h, f)
// ---------------------------------------------------------------------------
__global__ void qkv_kernel(const float* __restrict__ x,
                           const int* __restrict__ node_type,
                           const float* __restrict__ WQ,
                           const float* __restrict__ WK,
                           const float* __restrict__ WV) {
    int n = blockIdx.x;
    int tid = threadIdx.x;
    __shared__ float xs[DIM];
    xs[tid] = x[n * DIM + tid];
    __syncthreads();
    int t = node_type[n];
    int h = tid >> 4, f = tid & 15;
    const float* xr = xs + h * HD;
    int base = ((t * NH + h) * HD) * HD + f;
    float q = 0.f, k = 0.f, v = 0.f;
#pragma unroll
    for (int d = 0; d < HD; d++) {
        float xv = xr[d];
        q = fmaf(xv, WQ[base + d * HD], q);
        k = fmaf(xv, WK[base + d * HD], k);
        v = fmaf(xv, WV[base + d * HD], v);
    }
    gQ[n * DIM + tid] = q;
    gK[n * DIM + tid] = k;
    gV[n * DIM + tid] = v;
}

// ---------------------------------------------------------------------------
// CSR build
// ---------------------------------------------------------------------------
__global__ void hist_kernel(const int* __restrict__ ei, int E) {
    int e = blockIdx.x * blockDim.x + threadIdx.x;
    if (e < E) atomicAdd(&gCnt[ei[E + e]], 1);
}

__global__ void scan_local_kernel(int N) {
    __shared__ int sh[1024];
    int t = threadIdx.x;
    int i = blockIdx.x * 1024 + t;
    int v = (i < N) ? gCnt[i] : 0;
    sh[t] = v;
    __syncthreads();
#pragma unroll
    for (int off = 1; off < 1024; off <<= 1) {
        int add = (t >= off) ? sh[t - off] : 0;
        __syncthreads();
        sh[t] += add;
        __syncthreads();
    }
    if (i < N) gRow[i] = sh[t] - v;
    if (t == 1023) gBlkSum[blockIdx.x] = sh[1023];
}

__global__ void scan_block_kernel(int nblk) {
    __shared__ int sh[64];
    int t = threadIdx.x;
    int v = (t < nblk) ? gBlkSum[t] : 0;
    sh[t] = v;
    __syncthreads();
#pragma unroll
    for (int off = 1; off < 64; off <<= 1) {
        int add = (t >= off) ? sh[t - off] : 0;
        __syncthreads();
        sh[t] += add;
        __syncthreads();
    }
    gBlkOff[t] = sh[t] - v;
}

__global__ void scan_add_kernel(int N, int E) {
    int i = blockIdx.x * blockDim.x + threadIdx.x;
    if (i < N) gRow[i] += gBlkOff[i >> 10];
    if (i == 0) gRow[N] = E;
}

__global__ void fill_kernel(const int* __restrict__ ei, int E) {
    int e = blockIdx.x * blockDim.x + threadIdx.x;
    if (e < E) {
        int dst = ei[E + e];
        int p = atomicAdd(&gCur[dst], 1);
        gEid[gRow[dst] + p] = e;
    }
}

// ---------------------------------------------------------------------------
// fused attention with qt-trick: qt[et] = W_e^T q computed ONCE per dst,
// then score = k_src . qt  (gathers only K/V: 51MB working set, L2-resident)
// ---------------------------------------------------------------------------
__global__ void attn_kernel(const int* __restrict__ ei,
                            const int* __restrict__ etype,
                            const float* __restrict__ We,
                            const float* __restrict__ mu, int E) {
    int n = blockIdx.x;
    int tid = threadIdx.x;
    int h = tid >> 4, d = tid & 15;
    __shared__ float sq[DIM];
    __shared__ float sqt[NET][DIM];
    __shared__ int s_src[128];
    __shared__ int s_et[128];

    sq[tid] = gQ[n * DIM + tid];
    __syncthreads();
#pragma unroll
    for (int et = 0; et < NET; et++) {
        const float* w = We + (((et * NH + h) * HD) + d) * HD;
        const float* qr = sq + h * HD;
        float acc = 0.f;
#pragma unroll
        for (int f = 0; f < HD; f++) acc = fmaf(w[f], qr[f], acc);
        sqt[et][tid] = acc;
    }
    __syncthreads();

    float muh[NET];
#pragma unroll
    for (int et = 0; et < NET; et++) muh[et] = mu[h * NET + et] * 0.25f;

    float m = -3.402823466e38f, den = 0.f, acc = 0.f;
    int row0 = gRow[n], row1 = gRow[n + 1];
    for (int cs = row0; cs < row1; cs += 128) {
        int c = min(128, row1 - cs);
        if (tid < c) {
            int e = gEid[cs + tid];
            s_src[tid] = ei[e];
            s_et[tid] = etype[e];
        }
        __syncthreads();
        for (int j = 0; j < c; j++) {
            int src = s_src[j], et = s_et[j];
            float kt = gK[src * DIM + tid];
            float v  = gV[src * DIM + tid];
            float s = kt * sqt[et][tid];
            s += __shfl_xor_sync(0xffffffffu, s, 1);
            s += __shfl_xor_sync(0xffffffffu, s, 2);
            s += __shfl_xor_sync(0xffffffffu, s, 4);
            s += __shfl_xor_sync(0xffffffffu, s, 8);
            s *= muh[et];
            float newm = fmaxf(m, s);
            float scale = __expf(m - newm);
            float p = __expf(s - newm);
            den = den * scale + p;
            acc = fmaf(acc, scale, p * v);
            m = newm;
        }
        __syncthreads();
    }
    gAgg[n * DIM + tid] = acc / (den + 1e-10f);
}

// ---------------------------------------------------------------------------
// packed f32x2 FMA microkernel helpers (Blackwell FFMA2 — PTX-only pattern)
// ---------------------------------------------------------------------------
__device__ __forceinline__ unsigned long long dup2(float a) {
    unsigned long long r;
    unsigned ai = __float_as_uint(a);
    asm("mov.b64 %0, {%1, %1};" : "=l"(r) : "r"(ai));
    return r;
}
__device__ __forceinline__ void fma2(unsigned long long& acc,
                                     unsigned long long a,
                                     unsigned long long b) {
    asm("fma.rn.f32x2 %0, %1, %2, %0;" : "+l"(acc) : "l"(a), "l"(b));
}
__device__ __forceinline__ float lo2(unsigned long long v) {
    return __uint_as_float((unsigned)v);
}
__device__ __forceinline__ float hi2(unsigned long long v) {
    return __uint_as_float((unsigned)(v >> 32));
}

// 8x8 micro-tile inner product step over a 32-deep k tile in shared memory.
// As: [32][132] (k-major, m inner), Bs: [32][132] (k-major, n inner).
#define GEMM_K32_F32X2(As, Bs, acc2, ty, tx)                                   \
    _Pragma("unroll")                                                          \
    for (int k = 0; k < 32; k++) {                                             \
        float a[8];                                                            \
        *(float4*)&a[0] = *(const float4*)&As[k][(ty) * 8];                    \
        *(float4*)&a[4] = *(const float4*)&As[k][(ty) * 8 + 4];                \
        ulonglong2 b01 = *(const ulonglong2*)&Bs[k][(tx) * 8];                 \
        ulonglong2 b23 = *(const ulonglong2*)&Bs[k][(tx) * 8 + 4];             \
        unsigned long long bp[4] = {b01.x, b01.y, b23.x, b23.y};               \
        _Pragma("unroll")                                                      \
        for (int i = 0; i < 8; i++) {                                          \
            unsigned long long ad = dup2(a[i]);                                \
            _Pragma("unroll")                                                  \
            for (int jp = 0; jp < 4; jp++) fma2(acc2[i][jp], ad, bp[jp]);      \
        }                                                                      \
    }

// ---------------------------------------------------------------------------
// oproj: f32x2 GEMM (M x 128 x 128) + bias + residual + LN1 -> gHid
// ---------------------------------------------------------------------------
__global__ __launch_bounds__(256) void oproj_ln1_kernel(
        const float* __restrict__ x, const float* __restrict__ Wo,
        const float* __restrict__ bo, const float* __restrict__ g1,
        const float* __restrict__ bb1, int M) {
    __shared__ float As[32][132];
    __shared__ float Bs[32][132];
    int tid = threadIdx.x;
    int tx = tid & 15, ty = tid >> 4;
    int m0 = blockIdx.y * 128;
    unsigned long long acc2[8][4];
#pragma unroll
    for (int i = 0; i < 8; i++)
#pragma unroll
        for (int jp = 0; jp < 4; jp++) acc2[i][jp] = 0ull;

    for (int k0 = 0; k0 < 128; k0 += 32) {
#pragma unroll
        for (int l = tid; l < 1024; l += 256) {
            int m = l >> 3;
            int kq = (l & 7) << 2;
            int gm = m0 + m; if (gm >= M) gm = M - 1;
            float4 a = *(const float4*)(&gAgg[gm * 128 + k0 + kq]);
            As[kq][m] = a.x; As[kq + 1][m] = a.y; As[kq + 2][m] = a.z; As[kq + 3][m] = a.w;
        }
#pragma unroll
        for (int l = tid; l < 1024; l += 256) {
            int k = l >> 5;
            int nq = (l & 31) << 2;
            *(float4*)&Bs[k][nq] = *(const float4*)(&Wo[(k0 + k) * 128 + nq]);
        }
        __syncthreads();
        GEMM_K32_F32X2(As, Bs, acc2, ty, tx);
        __syncthreads();
    }
    // epilogue: bias + residual(x) + LayerNorm1 -> gHid
    float bl[8], g1l[8], b1l[8];
#pragma unroll
    for (int j = 0; j < 8; j++) {
        int gn = tx * 8 + j;
        bl[j] = bo[gn]; g1l[j] = g1[gn]; b1l[j] = bb1[gn];
    }
#pragma unroll
    for (int i = 0; i < 8; i++) {
        int gm = m0 + ty * 8 + i;
        int gms = (gm < M) ? gm : (M - 1);
        float yv[8];
#pragma unroll
        for (int jp = 0; jp < 4; jp++) {
            yv[2 * jp] = lo2(acc2[i][jp]);
            yv[2 * jp + 1] = hi2(acc2[i][jp]);
        }
        float ssum = 0.f;
#pragma unroll
        for (int j = 0; j < 8; j++) {
            yv[j] += bl[j] + x[gms * 128 + tx * 8 + j];
            ssum += yv[j];
        }
        ssum += __shfl_xor_sync(0xffffffffu, ssum, 1);
        ssum += __shfl_xor_sync(0xffffffffu, ssum, 2);
        ssum += __shfl_xor_sync(0xffffffffu, ssum, 4);
        ssum += __shfl_xor_sync(0xffffffffu, ssum, 8);
        float mean = ssum * (1.f / DIM);
        float s2 = 0.f;
#pragma unroll
        for (int j = 0; j < 8; j++) {
            float dv = yv[j] - mean;
            s2 = fmaf(dv, dv, s2);
        }
        s2 += __shfl_xor_sync(0xffffffffu, s2, 1);
        s2 += __shfl_xor_sync(0xffffffffu, s2, 2);
        s2 += __shfl_xor_sync(0xffffffffu, s2, 4);
        s2 += __shfl_xor_sync(0xffffffffu, s2, 8);
        float rstd = rsqrtf(s2 * (1.f / DIM) + 1e-5f);
        if (gm < M) {
            float o[8];
#pragma unroll
            for (int j = 0; j < 8; j++)
                o[j] = (yv[j] - mean) * rstd * g1l[j] + b1l[j];
            *(float4*)&gHid[gm * 128 + tx * 8]     = *(float4*)&o[0];
            *(float4*)&gHid[gm * 128 + tx * 8 + 4] = *(float4*)&o[4];
        }
    }
}

// ---------------------------------------------------------------------------
// FFN GEMM 1: gF1[M,512] = gelu(gHid[M,128] @ W1 + b1), f32x2
// ---------------------------------------------------------------------------
__global__ __launch_bounds__(256) void ffn1_kernel(
        const float* __restrict__ W1, const float* __restrict__ b1v, int M) {
    __shared__ float As[32][132];
    __shared__ float Bs[32][132];
    int tid = threadIdx.x;
    int tx = tid & 15, ty = tid >> 4;
    int m0 = blockIdx.y * 128;
    int n0 = blockIdx.x * 128;
    unsigned long long acc2[8][4];
#pragma unroll
    for (int i = 0; i < 8; i++)
#pragma unroll
        for (int jp = 0; jp < 4; jp++) acc2[i][jp] = 0ull;

    for (int k0 = 0; k0 < 128; k0 += 32) {
#pragma unroll
        for (int l = tid; l < 1024; l += 256) {
            int m = l >> 3;
            int kq = (l & 7) << 2;
            int gm = m0 + m; if (gm >= M) gm = M - 1;
            float4 a = *(const float4*)(&gHid[gm * 128 + k0 + kq]);
            As[kq][m] = a.x; As[kq + 1][m] = a.y; As[kq + 2][m] = a.z; As[kq + 3][m] = a.w;
        }
#pragma unroll
        for (int l = tid; l < 1024; l += 256) {
            int k = l >> 5;
            int nq = (l & 31) << 2;
            *(float4*)&Bs[k][nq] = *(const float4*)(&W1[(k0 + k) * 512 + n0 + nq]);
        }
        __syncthreads();
        GEMM_K32_F32X2(As, Bs, acc2, ty, tx);
        __syncthreads();
    }
#pragma unroll
    for (int i = 0; i < 8; i++) {
        int gm = m0 + ty * 8 + i;
        if (gm >= M) continue;
        float o[8];
#pragma unroll
        for (int jp = 0; jp < 4; jp++) {
            o[2 * jp] = lo2(acc2[i][jp]);
            o[2 * jp + 1] = hi2(acc2[i][jp]);
        }
#pragma unroll
        for (int j = 0; j < 8; j++) {
            int gn = n0 + tx * 8 + j;
            float v = o[j] + b1v[gn];
            o[j] = 0.5f * v * (1.f + erff(v * 0.7071067811865476f));  // exact gelu
        }
        *(float4*)&gF1[gm * 512 + n0 + tx * 8]     = *(float4*)&o[0];
        *(float4*)&gF1[gm * 512 + n0 + tx * 8 + 4] = *(float4*)&o[4];
    }
}

// ---------------------------------------------------------------------------
// FFN GEMM 2 + residual + fused LayerNorm2 -> d_out, f32x2
// ---------------------------------------------------------------------------
__global__ __launch_bounds__(256) void ffn2_ln2_kernel(
        const float* __restrict__ W2, const float* __restrict__ b2v,
        const float* __restrict__ g2, const float* __restrict__ bb2,
        float* __restrict__ out, int M) {
    __shared__ float As[32][132];
    __shared__ float Bs[32][132];
    int tid = threadIdx.x;
    int tx = tid & 15, ty = tid >> 4;
    int m0 = blockIdx.y * 128;
    unsigned long long acc2[8][4];
#pragma unroll
    for (int i = 0; i < 8; i++)
#pragma unroll
        for (int jp = 0; jp < 4; jp++) acc2[i][jp] = 0ull;

    for (int k0 = 0; k0 < 512; k0 += 32) {
#pragma unroll
        for (int l = tid; l < 1024; l += 256) {
            int m = l >> 3;
            int kq = (l & 7) << 2;
            int gm = m0 + m; if (gm >= M) gm = M - 1;
            float4 a = *(const float4*)(&gF1[gm * 512 + k0 + kq]);
            As[kq][m] = a.x; As[kq + 1][m] = a.y; As[kq + 2][m] = a.z; As[kq + 3][m] = a.w;
        }
#pragma unroll
        for (int l = tid; l < 1024; l += 256) {
            int k = l >> 5;
            int nq = (l & 31) << 2;
            *(float4*)&Bs[k][nq] = *(const float4*)(&W2[(k0 + k) * 128 + nq]);
        }
        __syncthreads();
        GEMM_K32_F32X2(As, Bs, acc2, ty, tx);
        __syncthreads();
    }

    // epilogue: residual + LayerNorm over complete rows (16-lane groups)
    float b2l[8], g2l[8], bbl[8];
#pragma unroll
    for (int j = 0; j < 8; j++) {
        int gn = tx * 8 + j;
        b2l[j] = b2v[gn]; g2l[j] = g2[gn]; bbl[j] = bb2[gn];
    }
#pragma unroll
    for (int i = 0; i < 8; i++) {
        int gm = m0 + ty * 8 + i;
        int gms = (gm < M) ? gm : (M - 1);
        float yv[8];
#pragma unroll
        for (int jp = 0; jp < 4; jp++) {
            yv[2 * jp] = lo2(acc2[i][jp]);
            yv[2 * jp + 1] = hi2(acc2[i][jp]);
        }
        float ssum = 0.f;
#pragma unroll
        for (int j = 0; j < 8; j++) {
            yv[j] += b2l[j] + gHid[gms * 128 + tx * 8 + j];
            ssum += yv[j];
        }
        ssum += __shfl_xor_sync(0xffffffffu, ssum, 1);
        ssum += __shfl_xor_sync(0xffffffffu, ssum, 2);
        ssum += __shfl_xor_sync(0xffffffffu, ssum, 4);
        ssum += __shfl_xor_sync(0xffffffffu, ssum, 8);
        float mean = ssum * (1.f / DIM);
        float s2 = 0.f;
#pragma unroll
        for (int j = 0; j < 8; j++) {
            float dv = yv[j] - mean;
            s2 = fmaf(dv, dv, s2);
        }
        s2 += __shfl_xor_sync(0xffffffffu, s2, 1);
        s2 += __shfl_xor_sync(0xffffffffu, s2, 2);
        s2 += __shfl_xor_sync(0xffffffffu, s2, 4);
        s2 += __shfl_xor_sync(0xffffffffu, s2, 8);
        float rstd = rsqrtf(s2 * (1.f / DIM) + 1e-5f);
        if (gm < M) {
            float o[8];
#pragma unroll
            for (int j = 0; j < 8; j++)
                o[j] = (yv[j] - mean) * rstd * g2l[j] + bbl[j];
            *(float4*)&out[gm * 128 + tx * 8]     = *(float4*)&o[0];
            *(float4*)&out[gm * 128 + tx * 8 + 4] = *(float4*)&o[4];
        }
    }
}

// ---------------------------------------------------------------------------
extern "C" void kernel_launch(void* const* d_in, const int* in_sizes, int n_in,
                              void* d_out, int out_size) {
    const float* x     = (const float*)d_in[0];
    const int*   ei    = (const int*)d_in[1];
    const int*   etype = (const int*)d_in[2];
    const int*   ntype = (const int*)d_in[3];
    const float* WQ    = (const float*)d_in[4];
    const float* WK    = (const float*)d_in[5];
    const float* WV    = (const float*)d_in[6];
    const float* We    = (const float*)d_in[7];
    const float* mu    = (const float*)d_in[8];
    const float* Wo    = (const float*)d_in[9];
    const float* bo    = (const float*)d_in[10];
    const float* ln1g  = (const float*)d_in[11];
    const float* ln1b  = (const float*)d_in[12];
    const float* W1    = (const float*)d_in[13];
    const float* b1    = (const float*)d_in[14];
    const float* W2    = (const float*)d_in[15];
    const float* b2    = (const float*)d_in[16];
    const float* ln2g  = (const float*)d_in[17];
    const float* ln2b  = (const float*)d_in[18];

    int N = in_sizes[0] / DIM;   // 50000
    int E = in_sizes[1] / 2;     // 800000
    int nblk = (N + 1023) / 1024;
    int mtiles = (N + 127) / 128;

    init_kernel<<<(N + 255) / 256, 256>>>(N);
    qkv_kernel<<<N, 128>>>(x, ntype, WQ, WK, WV);
    hist_kernel<<<(E + 255) / 256, 256>>>(ei, E);
    scan_local_kernel<<<nblk, 1024>>>(N);
    scan_block_kernel<<<1, 64>>>(nblk);
    scan_add_kernel<<<(N + 255) / 256, 256>>>(N, E);
    fill_kernel<<<(E + 255) / 256, 256>>>(ei, E);
    attn_kernel<<<N, 128>>>(ei, etype, We, mu, E);
    oproj_ln1_kernel<<<dim3(1, mtiles), 256>>>(x, Wo, bo, ln1g, ln1b, N);
    ffn1_kernel<<<dim3(4, mtiles), 256>>>(W1, b1, N);
    ffn2_ln2_kernel<<<dim3(1, mtiles), 256>>>(W2, b2, ln2g, ln2b, (float*)d_out, N);
}

// round 5
// speedup vs baseline: 1.9840x; 1.9840x over previous
#include <cuda_runtime.h>
#include <math.h>

#define NN 50000
#define NE 800000
#define DIM 128
#define NH 8
#define HD 16
#define NET 5

// ---- scratch (device globals; no allocation allowed) ----
__device__ float gQ[NN * DIM];
__device__ float gV[NN * DIM];
__device__ float gKt[NET * NN * DIM];   // K transformed by each edge-type matrix
__device__ float gAgg[NN * DIM];
__device__ float gHid[NN * DIM];
__device__ float gF1[NN * 4 * DIM];
__device__ int   gEid[NE];
__device__ int   gCnt[NN];
__device__ int   gCur[NN];
__device__ int   gRow[NN + 1];
__device__ int   gBlkSum[64];
__device__ int   gBlkOff[64];

// ---------------------------------------------------------------------------
__global__ void init_kernel(int N) {
    int i = blockIdx.x * blockDim.x + threadIdx.x;
    if (i < N) { gCnt[i] = 0; gCur[i] = 0; }
}

// ---------------------------------------------------------------------------
// per-node-type QKV + per-edge-type K transform (all 5 types precomputed)
// one block (128 thr) per node; thread = (h, f)
// ---------------------------------------------------------------------------
__global__ void qkv_kt_kernel(const float* __restrict__ x,
                              const int* __restrict__ node_type,
                              const float* __restrict__ WQ,
                              const float* __restrict__ WK,
                              const float* __restrict__ WV,
                              const float* __restrict__ We) {
    int n = blockIdx.x;
    int tid = threadIdx.x;
    __shared__ float xs[DIM];
    __shared__ float ks[DIM];
    xs[tid] = x[n * DIM + tid];
    __syncthreads();
    int t = node_type[n];
    int h = tid >> 4, f = tid & 15;
    const float* xr = xs + h * HD;
    int base = ((t * NH + h) * HD) * HD + f;
    float q = 0.f, k = 0.f, v = 0.f;
#pragma unroll
    for (int d = 0; d < HD; d++) {
        float xv = xr[d];
        q = fmaf(xv, WQ[base + d * HD], q);
        k = fmaf(xv, WK[base + d * HD], k);
        v = fmaf(xv, WV[base + d * HD], v);
    }
    gQ[n * DIM + tid] = q;
    gV[n * DIM + tid] = v;
    ks[tid] = k;
    __syncthreads();
    const float* kr = ks + h * HD;
#pragma unroll
    for (int et = 0; et < NET; et++) {
        const float* w = We + ((et * NH + h) * HD) * HD + f;
        float acc = 0.f;
#pragma unroll
        for (int d = 0; d < HD; d++) acc = fmaf(kr[d], w[d * HD], acc);
        gKt[(et * NN + n) * DIM + tid] = acc;
    }
}

// ---------------------------------------------------------------------------
// CSR build
// ---------------------------------------------------------------------------
__global__ void hist_kernel(const int* __restrict__ ei, int E) {
    int e = blockIdx.x * blockDim.x + threadIdx.x;
    if (e < E) atomicAdd(&gCnt[ei[E + e]], 1);
}

__global__ void scan_local_kernel(int N) {
    __shared__ int sh[1024];
    int t = threadIdx.x;
    int i = blockIdx.x * 1024 + t;
    int v = (i < N) ? gCnt[i] : 0;
    sh[t] = v;
    __syncthreads();
#pragma unroll
    for (int off = 1; off < 1024; off <<= 1) {
        int add = (t >= off) ? sh[t - off] : 0;
        __syncthreads();
        sh[t] += add;
        __syncthreads();
    }
    if (i < N) gRow[i] = sh[t] - v;
    if (t == 1023) gBlkSum[blockIdx.x] = sh[1023];
}

__global__ void scan_block_kernel(int nblk) {
    __shared__ int sh[64];
    int t = threadIdx.x;
    int v = (t < nblk) ? gBlkSum[t] : 0;
    sh[t] = v;
    __syncthreads();
#pragma unroll
    for (int off = 1; off < 64; off <<= 1) {
        int add = (t >= off) ? sh[t - off] : 0;
        __syncthreads();
        sh[t] += add;
        __syncthreads();
    }
    gBlkOff[t] = sh[t] - v;
}

__global__ void scan_add_kernel(int N, int E) {
    int i = blockIdx.x * blockDim.x + threadIdx.x;
    if (i < N) gRow[i] += gBlkOff[i >> 10];
    if (i == 0) gRow[N] = E;
}

__global__ void fill_kernel(const int* __restrict__ ei, int E) {
    int e = blockIdx.x * blockDim.x + threadIdx.x;
    if (e < E) {
        int dst = ei[E + e];
        int p = atomicAdd(&gCur[dst], 1);
        gEid[gRow[dst] + p] = e;
    }
}

// ---------------------------------------------------------------------------
// fused attention: per-dst block (128 thr), online softmax, no atomics
// (R2 structure: per-node K-transform amortized via gKt precompute)
// ---------------------------------------------------------------------------
__global__ void attn_kernel(const int* __restrict__ ei,
                            const int* __restrict__ etype,
                            const float* __restrict__ mu, int E) {
    int n = blockIdx.x;
    int tid = threadIdx.x;
    int h = tid >> 4;
    __shared__ int s_src[128];
    __shared__ int s_et[128];
    float q = gQ[n * DIM + tid];
    float muh[NET];
#pragma unroll
    for (int et = 0; et < NET; et++) muh[et] = mu[h * NET + et] * 0.25f;

    float m = -3.402823466e38f, den = 0.f, acc = 0.f;
    int row0 = gRow[n], row1 = gRow[n + 1];
    for (int cs = row0; cs < row1; cs += 128) {
        int c = min(128, row1 - cs);
        if (tid < c) {
            int e = gEid[cs + tid];
            s_src[tid] = ei[e];
            s_et[tid] = etype[e];
        }
        __syncthreads();
        for (int j = 0; j < c; j++) {
            int src = s_src[j], et = s_et[j];
            float kt = gKt[(et * NN + src) * DIM + tid];
            float v  = gV[src * DIM + tid];
            float s = q * kt;
            s += __shfl_xor_sync(0xffffffffu, s, 1);
            s += __shfl_xor_sync(0xffffffffu, s, 2);
            s += __shfl_xor_sync(0xffffffffu, s, 4);
            s += __shfl_xor_sync(0xffffffffu, s, 8);
            s *= muh[et];
            float newm = fmaxf(m, s);
            float scale = __expf(m - newm);
            float p = __expf(s - newm);
            den = den * scale + p;
            acc = fmaf(acc, scale, p * v);
            m = newm;
        }
        __syncthreads();
    }
    gAgg[n * DIM + tid] = acc / (den + 1e-10f);
}

// ---------------------------------------------------------------------------
// oproj: tiled SIMT GEMM (M x 128 x 128) + bias + residual + LN1 -> gHid
// ---------------------------------------------------------------------------
__global__ void oproj_ln1_kernel(const float* __restrict__ x,
                                 const float* __restrict__ Wo,
                                 const float* __restrict__ bo,
                                 const float* __restrict__ g1,
                                 const float* __restrict__ bb1, int M) {
    __shared__ float As[32][132];
    __shared__ float Bs[32][132];
    int tid = threadIdx.x;
    int tx = tid & 15, ty = tid >> 4;
    int m0 = blockIdx.y * 128;
    float acc[8][8];
#pragma unroll
    for (int i = 0; i < 8; i++)
#pragma unroll
        for (int j = 0; j < 8; j++) acc[i][j] = 0.f;

    for (int k0 = 0; k0 < 128; k0 += 32) {
#pragma unroll
        for (int l = tid; l < 1024; l += 256) {
            int m = l >> 3;
            int kq = (l & 7) << 2;
            int gm = m0 + m; if (gm >= M) gm = M - 1;
            float4 a = *(const float4*)(&gAgg[gm * 128 + k0 + kq]);
            As[kq][m] = a.x; As[kq + 1][m] = a.y; As[kq + 2][m] = a.z; As[kq + 3][m] = a.w;
        }
#pragma unroll
        for (int l = tid; l < 1024; l += 256) {
            int k = l >> 5;
            int nq = (l & 31) << 2;
            *(float4*)&Bs[k][nq] = *(const float4*)(&Wo[(k0 + k) * 128 + nq]);
        }
        __syncthreads();
#pragma unroll
        for (int k = 0; k < 32; k++) {
            float a[8], b[8];
            *(float4*)&a[0] = *(const float4*)&As[k][ty * 8];
            *(float4*)&a[4] = *(const float4*)&As[k][ty * 8 + 4];
            *(float4*)&b[0] = *(const float4*)&Bs[k][tx * 8];
            *(float4*)&b[4] = *(const float4*)&Bs[k][tx * 8 + 4];
#pragma unroll
            for (int i = 0; i < 8; i++)
#pragma unroll
                for (int j = 0; j < 8; j++) acc[i][j] = fmaf(a[i], b[j], acc[i][j]);
        }
        __syncthreads();
    }
    float bl[8], g1l[8], b1l[8];
#pragma unroll
    for (int j = 0; j < 8; j++) {
        int gn = tx * 8 + j;
        bl[j] = bo[gn]; g1l[j] = g1[gn]; b1l[j] = bb1[gn];
    }
#pragma unroll
    for (int i = 0; i < 8; i++) {
        int gm = m0 + ty * 8 + i;
        int gms = (gm < M) ? gm : (M - 1);
        float yv[8];
        float ssum = 0.f;
#pragma unroll
        for (int j = 0; j < 8; j++) {
            yv[j] = acc[i][j] + bl[j] + x[gms * 128 + tx * 8 + j];
            ssum += yv[j];
        }
        ssum += __shfl_xor_sync(0xffffffffu, ssum, 1);
        ssum += __shfl_xor_sync(0xffffffffu, ssum, 2);
        ssum += __shfl_xor_sync(0xffffffffu, ssum, 4);
        ssum += __shfl_xor_sync(0xffffffffu, ssum, 8);
        float mean = ssum * (1.f / DIM);
        float s2 = 0.f;
#pragma unroll
        for (int j = 0; j < 8; j++) {
            float dv = yv[j] - mean;
            s2 = fmaf(dv, dv, s2);
        }
        s2 += __shfl_xor_sync(0xffffffffu, s2, 1);
        s2 += __shfl_xor_sync(0xffffffffu, s2, 2);
        s2 += __shfl_xor_sync(0xffffffffu, s2, 4);
        s2 += __shfl_xor_sync(0xffffffffu, s2, 8);
        float rstd = rsqrtf(s2 * (1.f / DIM) + 1e-5f);
        if (gm < M) {
            float o[8];
#pragma unroll
            for (int j = 0; j < 8; j++)
                o[j] = (yv[j] - mean) * rstd * g1l[j] + b1l[j];
            *(float4*)&gHid[gm * 128 + tx * 8]     = *(float4*)&o[0];
            *(float4*)&gHid[gm * 128 + tx * 8 + 4] = *(float4*)&o[4];
        }
    }
}

// ---------------------------------------------------------------------------
// tf32 tensor-core machinery
// ---------------------------------------------------------------------------
__device__ __forceinline__ unsigned f2tf(float f) {
    unsigned r;
    asm("cvt.rna.tf32.f32 %0, %1;" : "=r"(r) : "f"(f));
    return r;
}
__device__ __forceinline__ void mma_tf32(float* c, const unsigned* a, const unsigned* b) {
    asm volatile(
        "mma.sync.aligned.m16n8k8.row.col.f32.tf32.tf32.f32 "
        "{%0,%1,%2,%3},{%4,%5,%6,%7},{%8,%9},{%0,%1,%2,%3};"
        : "+f"(c[0]), "+f"(c[1]), "+f"(c[2]), "+f"(c[3])
        : "r"(a[0]), "r"(a[1]), "r"(a[2]), "r"(a[3]), "r"(b[0]), "r"(b[1]));
}

// ---------------------------------------------------------------------------
// FFN1: gF1[M,512] = gelu(gHid[M,128] @ W1 + b1)
// 512 thr, 16 warps (4x4), warp tile 32x32, block 128x128, BK=32
// ---------------------------------------------------------------------------
__global__ void ffn1_tc(const float* __restrict__ W1,
                        const float* __restrict__ b1v, int M) {
    __shared__ unsigned As[128][36];
    __shared__ unsigned Bs[32][132];
    int tid = threadIdx.x, lane = tid & 31, wid = tid >> 5;
    int wy = (wid & 3) * 32, wx = (wid >> 2) * 32;
    int m0 = blockIdx.y * 128, n0 = blockIdx.x * 128;
    int r = lane >> 2, t = lane & 3;
    float c[2][4][4];
#pragma unroll
    for (int i = 0; i < 2; i++)
#pragma unroll
        for (int j = 0; j < 4; j++)
#pragma unroll
            for (int q = 0; q < 4; q++) c[i][j][q] = 0.f;

    for (int k0 = 0; k0 < 128; k0 += 32) {
#pragma unroll
        for (int l = tid; l < 1024; l += 512) {
            int m = l >> 3, kq = (l & 7) << 2;
            int gm = m0 + m; if (gm >= M) gm = M - 1;
            float4 a = *(const float4*)(&gHid[gm * 128 + k0 + kq]);
            As[m][kq] = f2tf(a.x); As[m][kq + 1] = f2tf(a.y);
            As[m][kq + 2] = f2tf(a.z); As[m][kq + 3] = f2tf(a.w);
        }
#pragma unroll
        for (int l = tid; l < 1024; l += 512) {
            int k = l >> 5, nq = (l & 31) << 2;
            float4 b = *(const float4*)(&W1[(k0 + k) * 512 + n0 + nq]);
            Bs[k][nq] = f2tf(b.x); Bs[k][nq + 1] = f2tf(b.y);
            Bs[k][nq + 2] = f2tf(b.z); Bs[k][nq + 3] = f2tf(b.w);
        }
        __syncthreads();
#pragma unroll
        for (int kk = 0; kk < 32; kk += 8) {
            unsigned af[2][4], bf[4][2];
#pragma unroll
            for (int i = 0; i < 2; i++) {
                af[i][0] = As[wy + i * 16 + r][kk + t];
                af[i][1] = As[wy + i * 16 + r + 8][kk + t];
                af[i][2] = As[wy + i * 16 + r][kk + t + 4];
                af[i][3] = As[wy + i * 16 + r + 8][kk + t + 4];
            }
#pragma unroll
            for (int j = 0; j < 4; j++) {
                bf[j][0] = Bs[kk + t][wx + j * 8 + r];
                bf[j][1] = Bs[kk + t + 4][wx + j * 8 + r];
            }
#pragma unroll
            for (int i = 0; i < 2; i++)
#pragma unroll
                for (int j = 0; j < 4; j++) mma_tf32(c[i][j], af[i], bf[j]);
        }
        __syncthreads();
    }
#pragma unroll
    for (int i = 0; i < 2; i++) {
        int row = m0 + wy + i * 16 + r;
        int row2 = row + 8;
#pragma unroll
        for (int j = 0; j < 4; j++) {
            int col = n0 + wx + j * 8 + 2 * t;
            float bc0 = b1v[col], bc1 = b1v[col + 1];
            if (row < M) {
                float v0 = c[i][j][0] + bc0;
                float v1 = c[i][j][1] + bc1;
                v0 = 0.5f * v0 * (1.f + erff(v0 * 0.7071067811865476f));
                v1 = 0.5f * v1 * (1.f + erff(v1 * 0.7071067811865476f));
                *(float2*)&gF1[row * 512 + col] = make_float2(v0, v1);
            }
            if (row2 < M) {
                float v0 = c[i][j][2] + bc0;
                float v1 = c[i][j][3] + bc1;
                v0 = 0.5f * v0 * (1.f + erff(v0 * 0.7071067811865476f));
                v1 = 0.5f * v1 * (1.f + erff(v1 * 0.7071067811865476f));
                *(float2*)&gF1[row2 * 512 + col] = make_float2(v0, v1);
            }
        }
    }
}

// ---------------------------------------------------------------------------
// FFN2: out = LN2(gHid + gF1[M,512] @ W2 + b2), 512 thr, fused LN epilogue
// ---------------------------------------------------------------------------
__global__ void ffn2_tc_ln2(const float* __restrict__ W2,
                            const float* __restrict__ b2v,
                            const float* __restrict__ g2,
                            const float* __restrict__ bb2,
                            float* __restrict__ out, int M) {
    __shared__ unsigned As[128][36];
    __shared__ unsigned Bs[32][132];
    __shared__ float rs[4][128];
    __shared__ float rq[4][128];
    int tid = threadIdx.x, lane = tid & 31, wid = tid >> 5;
    int wy = (wid & 3) * 32, wxg = wid >> 2;
    int wx = wxg * 32;
    int m0 = blockIdx.y * 128;
    int r = lane >> 2, t = lane & 3;
    float c[2][4][4];
#pragma unroll
    for (int i = 0; i < 2; i++)
#pragma unroll
        for (int j = 0; j < 4; j++)
#pragma unroll
            for (int q = 0; q < 4; q++) c[i][j][q] = 0.f;

    for (int k0 = 0; k0 < 512; k0 += 32) {
#pragma unroll
        for (int l = tid; l < 1024; l += 512) {
            int m = l >> 3, kq = (l & 7) << 2;
            int gm = m0 + m; if (gm >= M) gm = M - 1;
            float4 a = *(const float4*)(&gF1[gm * 512 + k0 + kq]);
            As[m][kq] = f2tf(a.x); As[m][kq + 1] = f2tf(a.y);
            As[m][kq + 2] = f2tf(a.z); As[m][kq + 3] = f2tf(a.w);
        }
#pragma unroll
        for (int l = tid; l < 1024; l += 512) {
            int k = l >> 5, nq = (l & 31) << 2;
            float4 b = *(const float4*)(&W2[(k0 + k) * 128 + nq]);
            Bs[k][nq] = f2tf(b.x); Bs[k][nq + 1] = f2tf(b.y);
            Bs[k][nq + 2] = f2tf(b.z); Bs[k][nq + 3] = f2tf(b.w);
        }
        __syncthreads();
#pragma unroll
        for (int kk = 0; kk < 32; kk += 8) {
            unsigned af[2][4], bf[4][2];
#pragma unroll
            for (int i = 0; i < 2; i++) {
                af[i][0] = As[wy + i * 16 + r][kk + t];
                af[i][1] = As[wy + i * 16 + r + 8][kk + t];
                af[i][2] = As[wy + i * 16 + r][kk + t + 4];
                af[i][3] = As[wy + i * 16 + r + 8][kk + t + 4];
            }
#pragma unroll
            for (int j = 0; j < 4; j++) {
                bf[j][0] = Bs[kk + t][wx + j * 8 + r];
                bf[j][1] = Bs[kk + t + 4][wx + j * 8 + r];
            }
#pragma unroll
            for (int i = 0; i < 2; i++)
#pragma unroll
                for (int j = 0; j < 4; j++) mma_tf32(c[i][j], af[i], bf[j]);
        }
        __syncthreads();
    }

    // epilogue: y = c + b2 + gHid; per-row LN over 128 cols (4 warps/row)
    float sum[2][2] = {{0.f, 0.f}, {0.f, 0.f}};
    float sq2[2][2] = {{0.f, 0.f}, {0.f, 0.f}};
#pragma unroll
    for (int i = 0; i < 2; i++) {
        int row = m0 + wy + i * 16 + r;
        int rowc  = (row < M) ? row : (M - 1);
        int row2c = (row + 8 < M) ? (row + 8) : (M - 1);
#pragma unroll
        for (int j = 0; j < 4; j++) {
            int col = wx + j * 8 + 2 * t;
            float bc0 = b2v[col], bc1 = b2v[col + 1];
            float2 h0 = *(const float2*)&gHid[rowc * 128 + col];
            float2 h1 = *(const float2*)&gHid[row2c * 128 + col];
            c[i][j][0] += bc0 + h0.x;
            c[i][j][1] += bc1 + h0.y;
            c[i][j][2] += bc0 + h1.x;
            c[i][j][3] += bc1 + h1.y;
            sum[i][0] += c[i][j][0] + c[i][j][1];
            sum[i][1] += c[i][j][2] + c[i][j][3];
            sq2[i][0] = fmaf(c[i][j][0], c[i][j][0], fmaf(c[i][j][1], c[i][j][1], sq2[i][0]));
            sq2[i][1] = fmaf(c[i][j][2], c[i][j][2], fmaf(c[i][j][3], c[i][j][3], sq2[i][1]));
        }
    }
#pragma unroll
    for (int i = 0; i < 2; i++) {
#pragma unroll
        for (int hl = 0; hl < 2; hl++) {
            sum[i][hl] += __shfl_xor_sync(0xffffffffu, sum[i][hl], 1);
            sum[i][hl] += __shfl_xor_sync(0xffffffffu, sum[i][hl], 2);
            sq2[i][hl] += __shfl_xor_sync(0xffffffffu, sq2[i][hl], 1);
            sq2[i][hl] += __shfl_xor_sync(0xffffffffu, sq2[i][hl], 2);
        }
    }
    if (t == 0) {
#pragma unroll
        for (int i = 0; i < 2; i++) {
            rs[wxg][wy + i * 16 + r]     = sum[i][0];
            rs[wxg][wy + i * 16 + r + 8] = sum[i][1];
            rq[wxg][wy + i * 16 + r]     = sq2[i][0];
            rq[wxg][wy + i * 16 + r + 8] = sq2[i][1];
        }
    }
    __syncthreads();
#pragma unroll
    for (int i = 0; i < 2; i++) {
#pragma unroll
        for (int hl = 0; hl < 2; hl++) {
            int rl = wy + i * 16 + r + hl * 8;
            int row = m0 + rl;
            float s  = rs[0][rl] + rs[1][rl] + rs[2][rl] + rs[3][rl];
            float s2 = rq[0][rl] + rq[1][rl] + rq[2][rl] + rq[3][rl];
            float mean = s * (1.f / DIM);
            float var = s2 * (1.f / DIM) - mean * mean;
            float rstd = rsqrtf(var + 1e-5f);
            if (row < M) {
#pragma unroll
                for (int j = 0; j < 4; j++) {
                    int col = wx + j * 8 + 2 * t;
                    float y0 = c[i][j][hl * 2 + 0];
                    float y1 = c[i][j][hl * 2 + 1];
                    float o0 = (y0 - mean) * rstd * g2[col] + bb2[col];
                    float o1 = (y1 - mean) * rstd * g2[col + 1] + bb2[col + 1];
                    *(float2*)&out[row * 128 + col] = make_float2(o0, o1);
                }
            }
        }
    }
}

// ---------------------------------------------------------------------------
extern "C" void kernel_launch(void* const* d_in, const int* in_sizes, int n_in,
                              void* d_out, int out_size) {
    const float* x     = (const float*)d_in[0];
    const int*   ei    = (const int*)d_in[1];
    const int*   etype = (const int*)d_in[2];
    const int*   ntype = (const int*)d_in[3];
    const float* WQ    = (const float*)d_in[4];
    const float* WK    = (const float*)d_in[5];
    const float* WV    = (const float*)d_in[6];
    const float* We    = (const float*)d_in[7];
    const float* mu    = (const float*)d_in[8];
    const float* Wo    = (const float*)d_in[9];
    const float* bo    = (const float*)d_in[10];
    const float* ln1g  = (const float*)d_in[11];
    const float* ln1b  = (const float*)d_in[12];
    const float* W1    = (const float*)d_in[13];
    const float* b1    = (const float*)d_in[14];
    const float* W2    = (const float*)d_in[15];
    const float* b2    = (const float*)d_in[16];
    const float* ln2g  = (const float*)d_in[17];
    const float* ln2b  = (const float*)d_in[18];

    int N = in_sizes[0] / DIM;   // 50000
    int E = in_sizes[1] / 2;     // 800000
    int nblk = (N + 1023) / 1024;
    int mtiles = (N + 127) / 128;

    init_kernel<<<(N + 255) / 256, 256>>>(N);
    qkv_kt_kernel<<<N, 128>>>(x, ntype, WQ, WK, WV, We);
    hist_kernel<<<(E + 255) / 256, 256>>>(ei, E);
    scan_local_kernel<<<nblk, 1024>>>(N);
    scan_block_kernel<<<1, 64>>>(nblk);
    scan_add_kernel<<<(N + 255) / 256, 256>>>(N, E);
    fill_kernel<<<(E + 255) / 256, 256>>>(ei, E);
    attn_kernel<<<N, 128>>>(ei, etype, mu, E);
    oproj_ln1_kernel<<<dim3(1, mtiles), 256>>>(x, Wo, bo, ln1g, ln1b, N);
    ffn1_tc<<<dim3(4, mtiles), 512>>>(W1, b1, N);
    ffn2_tc_ln2<<<dim3(1, mtiles), 512>>>(W2, b2, ln2g, ln2b, (float*)d_out, N);
}

// round 6
// speedup vs baseline: 2.1004x; 1.0587x over previous
#include <cuda_runtime.h>
#include <cuda_fp16.h>
#include <math.h>

#define NN 50000
#define NE 800000
#define DIM 128
#define NH 8
#define HD 16
#define NET 5

// ---- scratch (device globals; no allocation allowed) ----
__device__ float  gQ[NN * DIM];
__device__ __half gKtH[NET * NN * DIM];  // K transformed, fp16 (64MB, L2-friendly)
__device__ __half gVH[NN * DIM];         // V, fp16 (12.8MB)
__device__ float  gAgg[NN * DIM];
__device__ float  gHid[NN * DIM];
__device__ float  gF1[NN * 4 * DIM];
__device__ int    gEid[NE];
__device__ int    gCnt[NN];
__device__ int    gCur[NN];
__device__ int    gRow[NN + 1];
__device__ int    gBlkSum[64];
__device__ int    gBlkOff[64];

// ---------------------------------------------------------------------------
__global__ void init_kernel(int N) {
    int i = blockIdx.x * blockDim.x + threadIdx.x;
    if (i < N) { gCnt[i] = 0; gCur[i] = 0; }
}

// ---------------------------------------------------------------------------
// per-node-type QKV + per-edge-type K transform (all 5 types precomputed)
// one block (128 thr) per node; thread = (h, f)
// ---------------------------------------------------------------------------
__global__ void qkv_kt_kernel(const float* __restrict__ x,
                              const int* __restrict__ node_type,
                              const float* __restrict__ WQ,
                              const float* __restrict__ WK,
                              const float* __restrict__ WV,
                              const float* __restrict__ We) {
    int n = blockIdx.x;
    int tid = threadIdx.x;
    __shared__ float xs[DIM];
    __shared__ float ks[DIM];
    xs[tid] = x[n * DIM + tid];
    __syncthreads();
    int t = node_type[n];
    int h = tid >> 4, f = tid & 15;
    const float* xr = xs + h * HD;
    int base = ((t * NH + h) * HD) * HD + f;
    float q = 0.f, k = 0.f, v = 0.f;
#pragma unroll
    for (int d = 0; d < HD; d++) {
        float xv = xr[d];
        q = fmaf(xv, WQ[base + d * HD], q);
        k = fmaf(xv, WK[base + d * HD], k);
        v = fmaf(xv, WV[base + d * HD], v);
    }
    gQ[n * DIM + tid] = q;
    gVH[n * DIM + tid] = __float2half(v);
    ks[tid] = k;
    __syncthreads();
    const float* kr = ks + h * HD;
#pragma unroll
    for (int et = 0; et < NET; et++) {
        const float* w = We + ((et * NH + h) * HD) * HD + f;
        float acc = 0.f;
#pragma unroll
        for (int d = 0; d < HD; d++) acc = fmaf(kr[d], w[d * HD], acc);
        gKtH[(et * NN + n) * DIM + tid] = __float2half(acc);
    }
}

// ---------------------------------------------------------------------------
// CSR build
// ---------------------------------------------------------------------------
__global__ void hist_kernel(const int* __restrict__ ei, int E) {
    int e = blockIdx.x * blockDim.x + threadIdx.x;
    if (e < E) atomicAdd(&gCnt[ei[E + e]], 1);
}

__global__ void scan_local_kernel(int N) {
    __shared__ int sh[1024];
    int t = threadIdx.x;
    int i = blockIdx.x * 1024 + t;
    int v = (i < N) ? gCnt[i] : 0;
    sh[t] = v;
    __syncthreads();
#pragma unroll
    for (int off = 1; off < 1024; off <<= 1) {
        int add = (t >= off) ? sh[t - off] : 0;
        __syncthreads();
        sh[t] += add;
        __syncthreads();
    }
    if (i < N) gRow[i] = sh[t] - v;
    if (t == 1023) gBlkSum[blockIdx.x] = sh[1023];
}

__global__ void scan_block_kernel(int nblk) {
    __shared__ int sh[64];
    int t = threadIdx.x;
    int v = (t < nblk) ? gBlkSum[t] : 0;
    sh[t] = v;
    __syncthreads();
#pragma unroll
    for (int off = 1; off < 64; off <<= 1) {
        int add = (t >= off) ? sh[t - off] : 0;
        __syncthreads();
        sh[t] += add;
        __syncthreads();
    }
    gBlkOff[t] = sh[t] - v;
}

__global__ void scan_add_kernel(int N, int E) {
    int i = blockIdx.x * blockDim.x + threadIdx.x;
    if (i < N) gRow[i] += gBlkOff[i >> 10];
    if (i == 0) gRow[N] = E;
}

__global__ void fill_kernel(const int* __restrict__ ei, int E) {
    int e = blockIdx.x * blockDim.x + threadIdx.x;
    if (e < E) {
        int dst = ei[E + e];
        int p = atomicAdd(&gCur[dst], 1);
        gEid[gRow[dst] + p] = e;
    }
}

// ---------------------------------------------------------------------------
// fused attention: per-dst block (128 thr), 3-phase tile softmax, no atomics.
// Phase 1: all scores (independent, pipelined). Phase 2: per-head max/exp/sum
// (one shuffle-reduce per tile instead of per edge). Phase 3: weighted V acc.
// ---------------------------------------------------------------------------
__global__ void attn_kernel(const int* __restrict__ ei,
                            const int* __restrict__ etype,
                            const float* __restrict__ mu, int E) {
    int n = blockIdx.x;
    int tid = threadIdx.x;
    int h = tid >> 4, f = tid & 15;
    __shared__ int s_src[128];
    __shared__ int s_et[128];
    __shared__ float s_sc[128][9];   // [edge][head], 9-stride: conflict-free
    float q = gQ[n * DIM + tid];
    float muh[NET];
#pragma unroll
    for (int et = 0; et < NET; et++) muh[et] = mu[h * NET + et] * 0.25f;

    float m = -3.402823466e38f, den = 0.f, acc = 0.f;
    int row0 = gRow[n], row1 = gRow[n + 1];
    for (int cs = row0; cs < row1; cs += 128) {
        int c = min(128, row1 - cs);
        if (tid < c) {
            int e = gEid[cs + tid];
            s_src[tid] = ei[e];
            s_et[tid] = etype[e];
        }
        __syncthreads();

        // ---- phase 1: scores for all edges in tile (independent iters) ----
        for (int j = 0; j < c; j++) {
            int src = s_src[j], et = s_et[j];
            float kt = __half2float(gKtH[(et * NN + src) * DIM + tid]);
            float s = q * kt;
            s += __shfl_xor_sync(0xffffffffu, s, 1);
            s += __shfl_xor_sync(0xffffffffu, s, 2);
            s += __shfl_xor_sync(0xffffffffu, s, 4);
            s += __shfl_xor_sync(0xffffffffu, s, 8);
            if (f == 0) s_sc[j][h] = s * muh[et];
        }
        __syncwarp();

        // ---- phase 2: per-head tile max, exp weights, denominator ----
        float tmax = -3.402823466e38f;
        for (int j = f; j < c; j += 16) tmax = fmaxf(tmax, s_sc[j][h]);
        tmax = fmaxf(tmax, __shfl_xor_sync(0xffffffffu, tmax, 1));
        tmax = fmaxf(tmax, __shfl_xor_sync(0xffffffffu, tmax, 2));
        tmax = fmaxf(tmax, __shfl_xor_sync(0xffffffffu, tmax, 4));
        tmax = fmaxf(tmax, __shfl_xor_sync(0xffffffffu, tmax, 8));
        float newm = fmaxf(m, tmax);
        float scale = __expf(m - newm);
        float dtile = 0.f;
        for (int j = f; j < c; j += 16) {
            float w = __expf(s_sc[j][h] - newm);
            s_sc[j][h] = w;
            dtile += w;
        }
        dtile += __shfl_xor_sync(0xffffffffu, dtile, 1);
        dtile += __shfl_xor_sync(0xffffffffu, dtile, 2);
        dtile += __shfl_xor_sync(0xffffffffu, dtile, 4);
        dtile += __shfl_xor_sync(0xffffffffu, dtile, 8);
        den = den * scale + dtile;
        acc *= scale;
        m = newm;
        __syncwarp();

        // ---- phase 3: weighted V accumulation (independent iters) ----
        for (int j = 0; j < c; j++) {
            float w = s_sc[j][h];
            float v = __half2float(gVH[s_src[j] * DIM + tid]);
            acc = fmaf(w, v, acc);
        }
        __syncthreads();
    }
    gAgg[n * DIM + tid] = acc / (den + 1e-10f);
}

// ---------------------------------------------------------------------------
// oproj: tiled SIMT GEMM (M x 128 x 128) + bias + residual + LN1 -> gHid
// ---------------------------------------------------------------------------
__global__ void oproj_ln1_kernel(const float* __restrict__ x,
                                 const float* __restrict__ Wo,
                                 const float* __restrict__ bo,
                                 const float* __restrict__ g1,
                                 const float* __restrict__ bb1, int M) {
    __shared__ float As[32][132];
    __shared__ float Bs[32][132];
    int tid = threadIdx.x;
    int tx = tid & 15, ty = tid >> 4;
    int m0 = blockIdx.y * 128;
    float acc[8][8];
#pragma unroll
    for (int i = 0; i < 8; i++)
#pragma unroll
        for (int j = 0; j < 8; j++) acc[i][j] = 0.f;

    for (int k0 = 0; k0 < 128; k0 += 32) {
#pragma unroll
        for (int l = tid; l < 1024; l += 256) {
            int m = l >> 3;
            int kq = (l & 7) << 2;
            int gm = m0 + m; if (gm >= M) gm = M - 1;
            float4 a = *(const float4*)(&gAgg[gm * 128 + k0 + kq]);
            As[kq][m] = a.x; As[kq + 1][m] = a.y; As[kq + 2][m] = a.z; As[kq + 3][m] = a.w;
        }
#pragma unroll
        for (int l = tid; l < 1024; l += 256) {
            int k = l >> 5;
            int nq = (l & 31) << 2;
            *(float4*)&Bs[k][nq] = *(const float4*)(&Wo[(k0 + k) * 128 + nq]);
        }
        __syncthreads();
#pragma unroll
        for (int k = 0; k < 32; k++) {
            float a[8], b[8];
            *(float4*)&a[0] = *(const float4*)&As[k][ty * 8];
            *(float4*)&a[4] = *(const float4*)&As[k][ty * 8 + 4];
            *(float4*)&b[0] = *(const float4*)&Bs[k][tx * 8];
            *(float4*)&b[4] = *(const float4*)&Bs[k][tx * 8 + 4];
#pragma unroll
            for (int i = 0; i < 8; i++)
#pragma unroll
                for (int j = 0; j < 8; j++) acc[i][j] = fmaf(a[i], b[j], acc[i][j]);
        }
        __syncthreads();
    }
    float bl[8], g1l[8], b1l[8];
#pragma unroll
    for (int j = 0; j < 8; j++) {
        int gn = tx * 8 + j;
        bl[j] = bo[gn]; g1l[j] = g1[gn]; b1l[j] = bb1[gn];
    }
#pragma unroll
    for (int i = 0; i < 8; i++) {
        int gm = m0 + ty * 8 + i;
        int gms = (gm < M) ? gm : (M - 1);
        float yv[8];
        float ssum = 0.f;
#pragma unroll
        for (int j = 0; j < 8; j++) {
            yv[j] = acc[i][j] + bl[j] + x[gms * 128 + tx * 8 + j];
            ssum += yv[j];
        }
        ssum += __shfl_xor_sync(0xffffffffu, ssum, 1);
        ssum += __shfl_xor_sync(0xffffffffu, ssum, 2);
        ssum += __shfl_xor_sync(0xffffffffu, ssum, 4);
        ssum += __shfl_xor_sync(0xffffffffu, ssum, 8);
        float mean = ssum * (1.f / DIM);
        float s2 = 0.f;
#pragma unroll
        for (int j = 0; j < 8; j++) {
            float dv = yv[j] - mean;
            s2 = fmaf(dv, dv, s2);
        }
        s2 += __shfl_xor_sync(0xffffffffu, s2, 1);
        s2 += __shfl_xor_sync(0xffffffffu, s2, 2);
        s2 += __shfl_xor_sync(0xffffffffu, s2, 4);
        s2 += __shfl_xor_sync(0xffffffffu, s2, 8);
        float rstd = rsqrtf(s2 * (1.f / DIM) + 1e-5f);
        if (gm < M) {
            float o[8];
#pragma unroll
            for (int j = 0; j < 8; j++)
                o[j] = (yv[j] - mean) * rstd * g1l[j] + b1l[j];
            *(float4*)&gHid[gm * 128 + tx * 8]     = *(float4*)&o[0];
            *(float4*)&gHid[gm * 128 + tx * 8 + 4] = *(float4*)&o[4];
        }
    }
}

// ---------------------------------------------------------------------------
// tf32 tensor-core machinery
// ---------------------------------------------------------------------------
__device__ __forceinline__ unsigned f2tf(float f) {
    unsigned r;
    asm("cvt.rna.tf32.f32 %0, %1;" : "=r"(r) : "f"(f));
    return r;
}
__device__ __forceinline__ void mma_tf32(float* c, const unsigned* a, const unsigned* b) {
    asm volatile(
        "mma.sync.aligned.m16n8k8.row.col.f32.tf32.tf32.f32 "
        "{%0,%1,%2,%3},{%4,%5,%6,%7},{%8,%9},{%0,%1,%2,%3};"
        : "+f"(c[0]), "+f"(c[1]), "+f"(c[2]), "+f"(c[3])
        : "r"(a[0]), "r"(a[1]), "r"(a[2]), "r"(a[3]), "r"(b[0]), "r"(b[1]));
}

// ---------------------------------------------------------------------------
// FFN1: gF1[M,512] = gelu(gHid[M,128] @ W1 + b1)
// 512 thr, 16 warps (4x4), warp tile 32x32, block 128x128, BK=32
// ---------------------------------------------------------------------------
__global__ void ffn1_tc(const float* __restrict__ W1,
                        const float* __restrict__ b1v, int M) {
    __shared__ unsigned As[128][36];
    __shared__ unsigned Bs[32][132];
    int tid = threadIdx.x, lane = tid & 31, wid = tid >> 5;
    int wy = (wid & 3) * 32, wx = (wid >> 2) * 32;
    int m0 = blockIdx.y * 128, n0 = blockIdx.x * 128;
    int r = lane >> 2, t = lane & 3;
    float c[2][4][4];
#pragma unroll
    for (int i = 0; i < 2; i++)
#pragma unroll
        for (int j = 0; j < 4; j++)
#pragma unroll
            for (int q = 0; q < 4; q++) c[i][j][q] = 0.f;

    for (int k0 = 0; k0 < 128; k0 += 32) {
#pragma unroll
        for (int l = tid; l < 1024; l += 512) {
            int m = l >> 3, kq = (l & 7) << 2;
            int gm = m0 + m; if (gm >= M) gm = M - 1;
            float4 a = *(const float4*)(&gHid[gm * 128 + k0 + kq]);
            As[m][kq] = f2tf(a.x); As[m][kq + 1] = f2tf(a.y);
            As[m][kq + 2] = f2tf(a.z); As[m][kq + 3] = f2tf(a.w);
        }
#pragma unroll
        for (int l = tid; l < 1024; l += 512) {
            int k = l >> 5, nq = (l & 31) << 2;
            float4 b = *(const float4*)(&W1[(k0 + k) * 512 + n0 + nq]);
            Bs[k][nq] = f2tf(b.x); Bs[k][nq + 1] = f2tf(b.y);
            Bs[k][nq + 2] = f2tf(b.z); Bs[k][nq + 3] = f2tf(b.w);
        }
        __syncthreads();
#pragma unroll
        for (int kk = 0; kk < 32; kk += 8) {
            unsigned af[2][4], bf[4][2];
#pragma unroll
            for (int i = 0; i < 2; i++) {
                af[i][0] = As[wy + i * 16 + r][kk + t];
                af[i][1] = As[wy + i * 16 + r + 8][kk + t];
                af[i][2] = As[wy + i * 16 + r][kk + t + 4];
                af[i][3] = As[wy + i * 16 + r + 8][kk + t + 4];
            }
#pragma unroll
            for (int j = 0; j < 4; j++) {
                bf[j][0] = Bs[kk + t][wx + j * 8 + r];
                bf[j][1] = Bs[kk + t + 4][wx + j * 8 + r];
            }
#pragma unroll
            for (int i = 0; i < 2; i++)
#pragma unroll
                for (int j = 0; j < 4; j++) mma_tf32(c[i][j], af[i], bf[j]);
        }
        __syncthreads();
    }
#pragma unroll
    for (int i = 0; i < 2; i++) {
        int row = m0 + wy + i * 16 + r;
        int row2 = row + 8;
#pragma unroll
        for (int j = 0; j < 4; j++) {
            int col = n0 + wx + j * 8 + 2 * t;
            float bc0 = b1v[col], bc1 = b1v[col + 1];
            if (row < M) {
                float v0 = c[i][j][0] + bc0;
                float v1 = c[i][j][1] + bc1;
                v0 = 0.5f * v0 * (1.f + erff(v0 * 0.7071067811865476f));
                v1 = 0.5f * v1 * (1.f + erff(v1 * 0.7071067811865476f));
                *(float2*)&gF1[row * 512 + col] = make_float2(v0, v1);
            }
            if (row2 < M) {
                float v0 = c[i][j][2] + bc0;
                float v1 = c[i][j][3] + bc1;
                v0 = 0.5f * v0 * (1.f + erff(v0 * 0.7071067811865476f));
                v1 = 0.5f * v1 * (1.f + erff(v1 * 0.7071067811865476f));
                *(float2*)&gF1[row2 * 512 + col] = make_float2(v0, v1);
            }
        }
    }
}

// ---------------------------------------------------------------------------
// FFN2: out = LN2(gHid + gF1[M,512] @ W2 + b2), 512 thr, fused LN epilogue
// ---------------------------------------------------------------------------
__global__ void ffn2_tc_ln2(const float* __restrict__ W2,
                            const float* __restrict__ b2v,
                            const float* __restrict__ g2,
                            const float* __restrict__ bb2,
                            float* __restrict__ out, int M) {
    __shared__ unsigned As[128][36];
    __shared__ unsigned Bs[32][132];
    __shared__ float rs[4][128];
    __shared__ float rq[4][128];
    int tid = threadIdx.x, lane = tid & 31, wid = tid >> 5;
    int wy = (wid & 3) * 32, wxg = wid >> 2;
    int wx = wxg * 32;
    int m0 = blockIdx.y * 128;
    int r = lane >> 2, t = lane & 3;
    float c[2][4][4];
#pragma unroll
    for (int i = 0; i < 2; i++)
#pragma unroll
        for (int j = 0; j < 4; j++)
#pragma unroll
            for (int q = 0; q < 4; q++) c[i][j][q] = 0.f;

    for (int k0 = 0; k0 < 512; k0 += 32) {
#pragma unroll
        for (int l = tid; l < 1024; l += 512) {
            int m = l >> 3, kq = (l & 7) << 2;
            int gm = m0 + m; if (gm >= M) gm = M - 1;
            float4 a = *(const float4*)(&gF1[gm * 512 + k0 + kq]);
            As[m][kq] = f2tf(a.x); As[m][kq + 1] = f2tf(a.y);
            As[m][kq + 2] = f2tf(a.z); As[m][kq + 3] = f2tf(a.w);
        }
#pragma unroll
        for (int l = tid; l < 1024; l += 512) {
            int k = l >> 5, nq = (l & 31) << 2;
            float4 b = *(const float4*)(&W2[(k0 + k) * 128 + nq]);
            Bs[k][nq] = f2tf(b.x); Bs[k][nq + 1] = f2tf(b.y);
            Bs[k][nq + 2] = f2tf(b.z); Bs[k][nq + 3] = f2tf(b.w);
        }
        __syncthreads();
#pragma unroll
        for (int kk = 0; kk < 32; kk += 8) {
            unsigned af[2][4], bf[4][2];
#pragma unroll
            for (int i = 0; i < 2; i++) {
                af[i][0] = As[wy + i * 16 + r][kk + t];
                af[i][1] = As[wy + i * 16 + r + 8][kk + t];
                af[i][2] = As[wy + i * 16 + r][kk + t + 4];
                af[i][3] = As[wy + i * 16 + r + 8][kk + t + 4];
            }
#pragma unroll
            for (int j = 0; j < 4; j++) {
                bf[j][0] = Bs[kk + t][wx + j * 8 + r];
                bf[j][1] = Bs[kk + t + 4][wx + j * 8 + r];
            }
#pragma unroll
            for (int i = 0; i < 2; i++)
#pragma unroll
                for (int j = 0; j < 4; j++) mma_tf32(c[i][j], af[i], bf[j]);
        }
        __syncthreads();
    }

    // epilogue: y = c + b2 + gHid; per-row LN over 128 cols (4 warps/row)
    float sum[2][2] = {{0.f, 0.f}, {0.f, 0.f}};
    float sq2[2][2] = {{0.f, 0.f}, {0.f, 0.f}};
#pragma unroll
    for (int i = 0; i < 2; i++) {
        int row = m0 + wy + i * 16 + r;
        int rowc  = (row < M) ? row : (M - 1);
        int row2c = (row + 8 < M) ? (row + 8) : (M - 1);
#pragma unroll
        for (int j = 0; j < 4; j++) {
            int col = wx + j * 8 + 2 * t;
            float bc0 = b2v[col], bc1 = b2v[col + 1];
            float2 h0 = *(const float2*)&gHid[rowc * 128 + col];
            float2 h1 = *(const float2*)&gHid[row2c * 128 + col];
            c[i][j][0] += bc0 + h0.x;
            c[i][j][1] += bc1 + h0.y;
            c[i][j][2] += bc0 + h1.x;
            c[i][j][3] += bc1 + h1.y;
            sum[i][0] += c[i][j][0] + c[i][j][1];
            sum[i][1] += c[i][j][2] + c[i][j][3];
            sq2[i][0] = fmaf(c[i][j][0], c[i][j][0], fmaf(c[i][j][1], c[i][j][1], sq2[i][0]));
            sq2[i][1] = fmaf(c[i][j][2], c[i][j][2], fmaf(c[i][j][3], c[i][j][3], sq2[i][1]));
        }
    }
#pragma unroll
    for (int i = 0; i < 2; i++) {
#pragma unroll
        for (int hl = 0; hl < 2; hl++) {
            sum[i][hl] += __shfl_xor_sync(0xffffffffu, sum[i][hl], 1);
            sum[i][hl] += __shfl_xor_sync(0xffffffffu, sum[i][hl], 2);
            sq2[i][hl] += __shfl_xor_sync(0xffffffffu, sq2[i][hl], 1);
            sq2[i][hl] += __shfl_xor_sync(0xffffffffu, sq2[i][hl], 2);
        }
    }
    if (t == 0) {
#pragma unroll
        for (int i = 0; i < 2; i++) {
            rs[wxg][wy + i * 16 + r]     = sum[i][0];
            rs[wxg][wy + i * 16 + r + 8] = sum[i][1];
            rq[wxg][wy + i * 16 + r]     = sq2[i][0];
            rq[wxg][wy + i * 16 + r + 8] = sq2[i][1];
        }
    }
    __syncthreads();
#pragma unroll
    for (int i = 0; i < 2; i++) {
#pragma unroll
        for (int hl = 0; hl < 2; hl++) {
            int rl = wy + i * 16 + r + hl * 8;
            int row = m0 + rl;
            float s  = rs[0][rl] + rs[1][rl] + rs[2][rl] + rs[3][rl];
            float s2 = rq[0][rl] + rq[1][rl] + rq[2][rl] + rq[3][rl];
            float mean = s * (1.f / DIM);
            float var = s2 * (1.f / DIM) - mean * mean;
            float rstd = rsqrtf(var + 1e-5f);
            if (row < M) {
#pragma unroll
                for (int j = 0; j < 4; j++) {
                    int col = wx + j * 8 + 2 * t;
                    float y0 = c[i][j][hl * 2 + 0];
                    float y1 = c[i][j][hl * 2 + 1];
                    float o0 = (y0 - mean) * rstd * g2[col] + bb2[col];
                    float o1 = (y1 - mean) * rstd * g2[col + 1] + bb2[col + 1];
                    *(float2*)&out[row * 128 + col] = make_float2(o0, o1);
                }
            }
        }
    }
}

// ---------------------------------------------------------------------------
extern "C" void kernel_launch(void* const* d_in, const int* in_sizes, int n_in,
                              void* d_out, int out_size) {
    const float* x     = (const float*)d_in[0];
    const int*   ei    = (const int*)d_in[1];
    const int*   etype = (const int*)d_in[2];
    const int*   ntype = (const int*)d_in[3];
    const float* WQ    = (const float*)d_in[4];
    const float* WK    = (const float*)d_in[5];
    const float* WV    = (const float*)d_in[6];
    const float* We    = (const float*)d_in[7];
    const float* mu    = (const float*)d_in[8];
    const float* Wo    = (const float*)d_in[9];
    const float* bo    = (const float*)d_in[10];
    const float* ln1g  = (const float*)d_in[11];
    const float* ln1b  = (const float*)d_in[12];
    const float* W1    = (const float*)d_in[13];
    const float* b1    = (const float*)d_in[14];
    const float* W2    = (const float*)d_in[15];
    const float* b2    = (const float*)d_in[16];
    const float* ln2g  = (const float*)d_in[17];
    const float* ln2b  = (const float*)d_in[18];

    int N = in_sizes[0] / DIM;   // 50000
    int E = in_sizes[1] / 2;     // 800000
    int nblk = (N + 1023) / 1024;
    int mtiles = (N + 127) / 128;

    init_kernel<<<(N + 255) / 256, 256>>>(N);
    qkv_kt_kernel<<<N, 128>>>(x, ntype, WQ, WK, WV, We);
    hist_kernel<<<(E + 255) / 256, 256>>>(ei, E);
    scan_local_kernel<<<nblk, 1024>>>(N);
    scan_block_kernel<<<1, 64>>>(nblk);
    scan_add_kernel<<<(N + 255) / 256, 256>>>(N, E);
    fill_kernel<<<(E + 255) / 256, 256>>>(ei, E);
    attn_kernel<<<N, 128>>>(ei, etype, mu, E);
    oproj_ln1_kernel<<<dim3(1, mtiles), 256>>>(x, Wo, bo, ln1g, ln1b, N);
    ffn1_tc<<<dim3(4, mtiles), 512>>>(W1, b1, N);
    ffn2_tc_ln2<<<dim3(1, mtiles), 512>>>(W2, b2, ln2g, ln2b, (float*)d_out, N);
}